// round 1
// baseline (speedup 1.0000x reference)
#include <cuda_runtime.h>
#include <cuda_bf16.h>
#include <math.h>

// Problem constants
#define BB_   4
#define HH_   64
#define WW_   64
#define CC_   512
#define CR_   64
#define HW_   4096          // H*W
#define NPIX_ 16384         // B*H*W

// ---------------------------------------------------------------------------
// Scratch (device globals; no allocation allowed)
// ---------------------------------------------------------------------------
__device__ float g_featsA[BB_ * CC_ * HW_];   // 33.5 MB
__device__ float g_featsB[BB_ * CC_ * HW_];   // 33.5 MB
__device__ float g_v[BB_ * CC_ * HW_];        // 33.5 MB
__device__ float g_q[BB_ * CR_ * HW_];        //  4.2 MB
__device__ float g_k[BB_ * CR_ * HW_];        //  4.2 MB
__device__ float g_attn[BB_ * HW_ * 128];     //  8.4 MB  (eH | eW per pixel)

typedef unsigned long long u64t;

// packed f32x2 helpers (FFMA2 path — only reachable via PTX on sm_103a)
__device__ __forceinline__ u64t pack2(float x, float y) {
    u64t r;
    asm("mov.b64 %0, {%1, %2};" : "=l"(r) : "f"(x), "f"(y));
    return r;
}
__device__ __forceinline__ void fma2(u64t& d, u64t a, u64t b) {
    asm("fma.rn.f32x2 %0, %1, %2, %0;" : "+l"(d) : "l"(a), "l"(b));
}

// ---------------------------------------------------------------------------
// Implicit-GEMM conv kernel (handles 3x3 SAME conv and 1x1 projections).
//   out[p, m] = sum_{tap, c} W[m, c, tap] * X[batch(p), c, shifted(p, tap)]
// EPI == 1 : BN + ReLU epilogue (e0=gamma, e1=beta, e2=mean, e3=var)
// EPI == 0 : bias epilogue (e0=bias)
// Tile: 128(M) x 128(N) x 8(K), 256 threads, 8x8 per thread, f32x2 inner loop.
// ---------------------------------------------------------------------------
template<int CIN, int TAPS, int EPI>
__global__ void __launch_bounds__(256, 2) conv_gemm(
    const float* __restrict__ X, const float* __restrict__ Wt,
    const float* __restrict__ e0, const float* __restrict__ e1,
    const float* __restrict__ e2, const float* __restrict__ e3,
    float* __restrict__ Y, int M)
{
    __shared__ float As[8][128];   // [k][m]
    __shared__ float Bs[8][128];   // [k][n]

    const int tid    = threadIdx.x;
    const int n_tile = blockIdx.x * 128;
    const int m_tile = blockIdx.y * 128;
    const int tx = tid & 15;       // n direction
    const int ty = tid >> 4;       // m direction

    u64t acc[8][4];
#pragma unroll
    for (int i = 0; i < 8; i++)
#pragma unroll
        for (int jp = 0; jp < 4; jp++) acc[i][jp] = 0ull;

    const int la = tid * 4;              // A-load linear base
    const int kB = (tid * 4) >> 7;       // B-load k row
    const int n0 = (tid * 4) & 127;      // B-load n base

    for (int tap = 0; tap < TAPS; ++tap) {
        const int dh = (TAPS == 9) ? (tap / 3 - 1) : 0;
        const int dw = (TAPS == 9) ? (tap % 3 - 1) : 0;

        for (int cb = 0; cb < CIN; cb += 8) {
            // --- load A tile (weights) ---
#pragma unroll
            for (int i = 0; i < 4; i++) {
                int l  = la + i;
                int m  = l >> 3, kk = l & 7;
                int mg = m_tile + m;
                float v = 0.f;
                if (mg < M) v = Wt[(mg * CIN + cb + kk) * TAPS + tap];
                As[kk][m] = v;
            }
            // --- load B tile (shifted input, zero-padded) ---
            {
                int cin = cb + kB;
#pragma unroll
                for (int i = 0; i < 4; i++) {
                    int p  = n_tile + n0 + i;
                    int bb = p >> 12, sp = p & 4095;
                    int hh = (sp >> 6) + dh;
                    int ww = (sp & 63) + dw;
                    float v = 0.f;
                    if ((unsigned)hh < 64u && (unsigned)ww < 64u)
                        v = X[(bb * CIN + cin) * HW_ + hh * 64 + ww];
                    Bs[kB][n0 + i] = v;
                }
            }
            __syncthreads();

#pragma unroll
            for (int kk = 0; kk < 8; kk++) {
                float4 a0 = *(const float4*)&As[kk][ty * 8];
                float4 a1 = *(const float4*)&As[kk][ty * 8 + 4];
                ulonglong2 q0 = *(const ulonglong2*)&Bs[kk][tx * 8];
                ulonglong2 q1 = *(const ulonglong2*)&Bs[kk][tx * 8 + 4];
                u64t bp0 = q0.x, bp1 = q0.y, bp2 = q1.x, bp3 = q1.y;
                float av[8] = {a0.x, a0.y, a0.z, a0.w, a1.x, a1.y, a1.z, a1.w};
#pragma unroll
                for (int i = 0; i < 8; i++) {
                    u64t ad = pack2(av[i], av[i]);
                    fma2(acc[i][0], ad, bp0);
                    fma2(acc[i][1], ad, bp1);
                    fma2(acc[i][2], ad, bp2);
                    fma2(acc[i][3], ad, bp3);
                }
            }
            __syncthreads();
        }
    }

    // --- epilogue ---
#pragma unroll
    for (int i = 0; i < 8; i++) {
        int mg = m_tile + ty * 8 + i;
        if (mg >= M) continue;
        float sc, sh;
        if (EPI == 1) {
            float s = e0[mg] * rsqrtf(e3[mg] + 1e-5f);
            sc = s;
            sh = e1[mg] - e2[mg] * s;
        } else {
            sc = 1.f;
            sh = e0[mg];
        }
#pragma unroll
        for (int jp = 0; jp < 4; jp++) {
            float lo = __uint_as_float((unsigned)(acc[i][jp] & 0xffffffffull));
            float hi = __uint_as_float((unsigned)(acc[i][jp] >> 32));
            float v0 = fmaf(lo, sc, sh);
            float v1 = fmaf(hi, sc, sh);
            if (EPI == 1) { v0 = fmaxf(v0, 0.f); v1 = fmaxf(v1, 0.f); }
            int p  = n_tile + tx * 8 + jp * 2;
            int bb = p >> 12, sp = p & 4095;
            *(float2*)&Y[(size_t)(bb * M + mg) * HW_ + sp] = make_float2(v0, v1);
        }
    }
}

// ---------------------------------------------------------------------------
// CCA energies: eH[b,h,w,i] = sum_c q[b,c,h,w] k[b,c,i,w]   (+NEG on i==h)
//               eW[b,h,w,j] = sum_c q[b,c,h,w] k[b,c,h,j]
// ---------------------------------------------------------------------------
__global__ void __launch_bounds__(256) energyH_kernel(
    const float* __restrict__ q, const float* __restrict__ k,
    float* __restrict__ attn)
{
    const int w = blockIdx.x, b = blockIdx.y;
    __shared__ float Qs[64][65];   // [c][h]
    __shared__ float Ks[64][65];   // [c][i]
    const int tid = threadIdx.x;
    for (int l = tid; l < 4096; l += 256) {
        int c = l >> 6, h = l & 63;
        int idx = ((b * 64 + c) * 64 + h) * 64 + w;
        Qs[c][h] = q[idx];
        Ks[c][h] = k[idx];
    }
    __syncthreads();
    const int hh = tid & 63, ig = tid >> 6;   // 4 groups of 16 i values
    float acc[16];
#pragma unroll
    for (int ii = 0; ii < 16; ii++) acc[ii] = 0.f;
    for (int c = 0; c < 64; c++) {
        float qv = Qs[c][hh];
#pragma unroll
        for (int ii = 0; ii < 16; ii++) acc[ii] += qv * Ks[c][ig * 16 + ii];
    }
    float* orow = attn + (size_t)(((b * 64 + hh) * 64 + w)) * 128;
#pragma unroll
    for (int ii = 0; ii < 16; ii++) {
        int i = ig * 16 + ii;
        orow[i] = acc[ii] + ((i == hh) ? -1000000000.0f : 0.f);
    }
}

__global__ void __launch_bounds__(256) energyW_kernel(
    const float* __restrict__ q, const float* __restrict__ k,
    float* __restrict__ attn)
{
    const int h = blockIdx.x, b = blockIdx.y;
    __shared__ float Qs[64][65];   // [c][w]
    __shared__ float Ks[64][65];   // [c][j]
    const int tid = threadIdx.x;
    for (int l = tid; l < 4096; l += 256) {
        int c = l >> 6, w = l & 63;
        int idx = ((b * 64 + c) * 64 + h) * 64 + w;
        Qs[c][w] = q[idx];
        Ks[c][w] = k[idx];
    }
    __syncthreads();
    const int wq = tid & 63, jg = tid >> 6;
    float acc[16];
#pragma unroll
    for (int jj = 0; jj < 16; jj++) acc[jj] = 0.f;
    for (int c = 0; c < 64; c++) {
        float qv = Qs[c][wq];
#pragma unroll
        for (int jj = 0; jj < 16; jj++) acc[jj] += qv * Ks[c][jg * 16 + jj];
    }
    float* orow = attn + (size_t)(((b * 64 + h) * 64 + wq)) * 128 + 64;
#pragma unroll
    for (int jj = 0; jj < 16; jj++) orow[jg * 16 + jj] = acc[jj];
}

// softmax over 128 values per pixel; one warp per pixel
__global__ void __launch_bounds__(256) softmax_kernel(float* __restrict__ attn)
{
    int gw = (blockIdx.x * blockDim.x + threadIdx.x) >> 5;
    if (gw >= NPIX_) return;
    int lane = threadIdx.x & 31;
    float* row = attn + (size_t)gw * 128;
    float v0 = row[lane], v1 = row[lane + 32], v2 = row[lane + 64], v3 = row[lane + 96];
    float mx = fmaxf(fmaxf(v0, v1), fmaxf(v2, v3));
#pragma unroll
    for (int o = 16; o > 0; o >>= 1) mx = fmaxf(mx, __shfl_xor_sync(0xffffffffu, mx, o));
    v0 = expf(v0 - mx); v1 = expf(v1 - mx); v2 = expf(v2 - mx); v3 = expf(v3 - mx);
    float s = v0 + v1 + v2 + v3;
#pragma unroll
    for (int o = 16; o > 0; o >>= 1) s += __shfl_xor_sync(0xffffffffu, s, o);
    float inv = 1.0f / s;
    row[lane] = v0 * inv; row[lane + 32] = v1 * inv;
    row[lane + 64] = v2 * inv; row[lane + 96] = v3 * inv;
}

// ---------------------------------------------------------------------------
// Aggregation:
//   aggH: fout = fin + gamma * sum_i v[b,c,i,w] * aH[b,h,w,i]
//   aggW: fout += gamma * sum_j v[b,c,h,j] * aW[b,h,w,j]
// 64-channel chunks per block; padded smem tiles.
// ---------------------------------------------------------------------------
__global__ void __launch_bounds__(256) aggH_kernel(
    const float* __restrict__ v, const float* __restrict__ attn,
    const float* __restrict__ fin, float* __restrict__ fout,
    const float* __restrict__ gptr)
{
    const int w = blockIdx.x, b = blockIdx.y, cb = blockIdx.z * 64;
    __shared__ float Vs[64][65];   // [c][i]
    __shared__ float Am[64][65];   // [h][i]
    const int tid = threadIdx.x;
    for (int l = tid; l < 4096; l += 256) {
        int c = l >> 6, i = l & 63;
        Vs[c][i] = v[(size_t)((b * CC_ + cb + c) * 64 + i) * 64 + w];
    }
    for (int l = tid; l < 4096; l += 256) {
        int h = l >> 6, i = l & 63;
        Am[h][i] = attn[(size_t)(((b * 64 + h) * 64 + w)) * 128 + i];
    }
    __syncthreads();
    const int tc = tid & 63, hg = tid >> 6;
    float acc[16];
#pragma unroll
    for (int t = 0; t < 16; t++) acc[t] = 0.f;
    for (int i = 0; i < 64; i++) {
        float vv = Vs[tc][i];
#pragma unroll
        for (int t = 0; t < 16; t++) acc[t] += vv * Am[hg * 16 + t][i];
    }
    const float g = *gptr;
#pragma unroll
    for (int t = 0; t < 16; t++) {
        int h = hg * 16 + t;
        size_t idx = (size_t)((b * CC_ + cb + tc) * 64 + h) * 64 + w;
        fout[idx] = fin[idx] + g * acc[t];
    }
}

__global__ void __launch_bounds__(256) aggW_kernel(
    const float* __restrict__ v, const float* __restrict__ attn,
    float* __restrict__ fout, const float* __restrict__ gptr)
{
    const int h = blockIdx.x, b = blockIdx.y, cb = blockIdx.z * 64;
    __shared__ float Vs[64][65];   // [c][j]
    __shared__ float Am[64][65];   // [w][j]
    const int tid = threadIdx.x;
    for (int l = tid; l < 4096; l += 256) {
        int c = l >> 6, j = l & 63;
        Vs[c][j] = v[(size_t)((b * CC_ + cb + c) * 64 + h) * 64 + j];
    }
    for (int l = tid; l < 4096; l += 256) {
        int w = l >> 6, j = l & 63;
        Am[w][j] = attn[(size_t)(((b * 64 + h) * 64 + w)) * 128 + 64 + j];
    }
    __syncthreads();
    const int tc = tid & 63, wg = tid >> 6;
    float acc[16];
#pragma unroll
    for (int t = 0; t < 16; t++) acc[t] = 0.f;
    for (int j = 0; j < 64; j++) {
        float vv = Vs[tc][j];
#pragma unroll
        for (int t = 0; t < 16; t++) acc[t] += vv * Am[wg * 16 + t][j];
    }
    const float g = *gptr;
#pragma unroll
    for (int t = 0; t < 16; t++) {
        int w = wg * 16 + t;
        size_t idx = (size_t)((b * CC_ + cb + tc) * 64 + h) * 64 + w;
        fout[idx] += g * acc[t];
    }
}

// ---------------------------------------------------------------------------
// Launch: conv1+bn+relu -> 2x CCA -> conv2+bn+relu
// ---------------------------------------------------------------------------
extern "C" void kernel_launch(void* const* d_in, const int* in_sizes, int n_in,
                              void* d_out, int out_size)
{
    const float* x     = (const float*)d_in[0];
    const float* c1w   = (const float*)d_in[1];
    const float* bn1g  = (const float*)d_in[2];
    const float* bn1b  = (const float*)d_in[3];
    const float* bn1m  = (const float*)d_in[4];
    const float* bn1v  = (const float*)d_in[5];
    const float* qw    = (const float*)d_in[6];
    const float* qb    = (const float*)d_in[7];
    const float* kw    = (const float*)d_in[8];
    const float* kb    = (const float*)d_in[9];
    const float* vw    = (const float*)d_in[10];
    const float* vb    = (const float*)d_in[11];
    const float* gamma = (const float*)d_in[12];
    const float* c2w   = (const float*)d_in[13];
    const float* bn2g  = (const float*)d_in[14];
    const float* bn2b  = (const float*)d_in[15];
    const float* bn2m  = (const float*)d_in[16];
    const float* bn2v  = (const float*)d_in[17];
    float* out = (float*)d_out;

    float *fA, *fB, *gq, *gk, *gv, *gat;
    cudaGetSymbolAddress((void**)&fA,  g_featsA);
    cudaGetSymbolAddress((void**)&fB,  g_featsB);
    cudaGetSymbolAddress((void**)&gq,  g_q);
    cudaGetSymbolAddress((void**)&gk,  g_k);
    cudaGetSymbolAddress((void**)&gv,  g_v);
    cudaGetSymbolAddress((void**)&gat, g_attn);

    const dim3 cgrid(128, 4);          // N=16384/128, M=512/128
    const dim3 pgrid1(128, 1);         // M=64 projections

    // conv1 + bn1 + relu : x(4,2048,64,64) -> featsA(4,512,64,64)
    conv_gemm<2048, 9, 1><<<cgrid, 256>>>(x, c1w, bn1g, bn1b, bn1m, bn1v, fA, CC_);

    float* cur = fA;
    float* nxt = fB;
    for (int it = 0; it < 2; ++it) {
        // projections (1x1 conv)
        conv_gemm<512, 1, 0><<<pgrid1, 256>>>(cur, qw, qb, nullptr, nullptr, nullptr, gq, CR_);
        conv_gemm<512, 1, 0><<<pgrid1, 256>>>(cur, kw, kb, nullptr, nullptr, nullptr, gk, CR_);
        conv_gemm<512, 1, 0><<<cgrid,  256>>>(cur, vw, vb, nullptr, nullptr, nullptr, gv, CC_);
        // energies + softmax
        energyH_kernel<<<dim3(64, 4), 256>>>(gq, gk, gat);
        energyW_kernel<<<dim3(64, 4), 256>>>(gq, gk, gat);
        softmax_kernel<<<NPIX_ / 8, 256>>>(gat);
        // aggregation + residual
        aggH_kernel<<<dim3(64, 4, 8), 256>>>(gv, gat, cur, nxt, gamma);
        aggW_kernel<<<dim3(64, 4, 8), 256>>>(gv, gat, nxt, gamma);
        float* tmp = cur; cur = nxt; nxt = tmp;
    }

    // conv2 + bn2 + relu : feats -> out
    conv_gemm<512, 9, 1><<<cgrid, 256>>>(cur, c2w, bn2g, bn2b, bn2m, bn2v, out, CC_);
}

// round 3
// speedup vs baseline: 6.3947x; 6.3947x over previous
#include <cuda_runtime.h>
#include <cuda_bf16.h>
#include <math.h>
#include <stdint.h>

#define HW_   4096
#define NPIX_ 16384

// Feature gate: tcgen05 only exists in the arch-specific (sm_103a/sm_100a) pass.
#if defined(__CUDA_ARCH__) && (defined(__CUDA_ARCH_FEAT_SM103_ALL) || defined(__CUDA_ARCH_FEAT_SM100_ALL))
#define HAS_TC 1
#else
#define HAS_TC 0
#endif

// ---------------------------------------------------------------------------
// Scratch (device globals; allocation is forbidden)
// ---------------------------------------------------------------------------
__device__ float g_featsA[4 * 512 * 4096];
__device__ float g_featsB[4 * 512 * 4096];
__device__ float g_v[4 * 512 * 4096];
__device__ float g_qk[4 * 128 * 4096];
__device__ float g_attn[4 * 4096 * 128];
__device__ float g_bqk[128];
__device__ __nv_bfloat16 g_xhi[4 * 4096 * 2048];
__device__ __nv_bfloat16 g_xlo[4 * 4096 * 2048];
__device__ __nv_bfloat16 g_fhi[4 * 4096 * 512];
__device__ __nv_bfloat16 g_flo[4 * 4096 * 512];
__device__ __nv_bfloat16 g_w1hi[9 * 512 * 2048];
__device__ __nv_bfloat16 g_w1lo[9 * 512 * 2048];
__device__ __nv_bfloat16 g_w2hi[9 * 512 * 512];
__device__ __nv_bfloat16 g_w2lo[9 * 512 * 512];
__device__ __nv_bfloat16 g_wqkhi[128 * 512];
__device__ __nv_bfloat16 g_wqklo[128 * 512];
__device__ __nv_bfloat16 g_wvhi[512 * 512];
__device__ __nv_bfloat16 g_wvlo[512 * 512];

// ---------------------------------------------------------------------------
// Generic PTX helpers (valid on base sm_103)
// ---------------------------------------------------------------------------
__device__ __forceinline__ unsigned smem_u32(const void* p) {
    unsigned a;
    asm("{ .reg .u64 t; cvta.to.shared.u64 t, %1; cvt.u32.u64 %0, t; }"
        : "=r"(a) : "l"(p));
    return a;
}
__device__ __forceinline__ unsigned elect_one() {
    unsigned p;
    asm volatile("{ .reg .pred p; elect.sync _|p, 0xFFFFFFFF; selp.b32 %0, 1, 0, p; }"
                 : "=r"(p));
    return p;
}
#define SW128(o) ((o) ^ (((o) >> 3) & 0x70))
__device__ __forceinline__ void mbar_init(unsigned mbar, unsigned cnt) {
    asm volatile("mbarrier.init.shared.b64 [%0], %1;" :: "r"(mbar), "r"(cnt) : "memory");
}
__device__ __forceinline__ void mbar_wait(unsigned mbar, unsigned phase) {
    asm volatile(
        "{\n\t.reg .pred P;\n\t"
        "WL_%=:\n\t"
        "mbarrier.try_wait.parity.acquire.cta.shared::cta.b64 P, [%0], %1, 0x989680;\n\t"
        "@P bra.uni WD_%=;\n\t"
        "bra.uni WL_%=;\n\t"
        "WD_%=:\n\t}"
        :: "r"(mbar), "r"(phase) : "memory");
}
__device__ __forceinline__ void fence_async_shared() {
    asm volatile("fence.proxy.async.shared::cta;" ::: "memory");
}

// ---------------------------------------------------------------------------
// tcgen05 helpers (arch-specific pass only)
// ---------------------------------------------------------------------------
#if HAS_TC
static constexpr unsigned long long SMEM_DESC_BASE_SW128 =
    (2ull << 61) | (1ull << 46) | (64ull << 32) | (1ull << 16);
__device__ __forceinline__ unsigned long long make_desc(unsigned addr) {
    return SMEM_DESC_BASE_SW128 | ((unsigned long long)(addr >> 4) & 0x3FFFull);
}
__device__ __forceinline__ void tmem_alloc(unsigned dst_smem, unsigned ncols) {
    asm volatile("tcgen05.alloc.cta_group::1.sync.aligned.shared::cta.b32 [%0], %1;"
                 :: "r"(dst_smem), "r"(ncols) : "memory");
}
__device__ __forceinline__ void tmem_dealloc(unsigned tmem, unsigned ncols) {
    asm volatile("tcgen05.dealloc.cta_group::1.sync.aligned.b32 %0, %1;"
                 :: "r"(tmem), "r"(ncols));
}
__device__ __forceinline__ void tc_commit(unsigned mbar) {
    asm volatile("tcgen05.commit.cta_group::1.mbarrier::arrive::one.shared::cluster.b64 [%0];"
                 :: "r"(mbar) : "memory");
}
__device__ __forceinline__ void tc_fence_after() {
    asm volatile("tcgen05.fence::after_thread_sync;" ::: "memory");
}
__device__ __forceinline__ void tc_wait_ld() {
    asm volatile("tcgen05.wait::ld.sync.aligned;" ::: "memory");
}
__device__ __forceinline__ void mma_ss_bf16(unsigned d, unsigned long long ad,
                                            unsigned long long bd, unsigned idesc,
                                            unsigned en) {
    asm volatile(
        "{\n\t.reg .pred p;\n\tsetp.ne.u32 p, %4, 0;\n\t"
        "tcgen05.mma.cta_group::1.kind::f16 [%0], %1, %2, %3, {%5, %5, %5, %5}, p;\n\t}"
        :: "r"(d), "l"(ad), "l"(bd), "r"(idesc), "r"(en), "r"(0u) : "memory");
}
__device__ __forceinline__ void tmem_ld32(unsigned* r, unsigned addr) {
    asm volatile(
        "tcgen05.ld.sync.aligned.32x32b.x32.b32 "
        "{%0, %1, %2, %3, %4, %5, %6, %7, "
        " %8, %9, %10, %11, %12, %13, %14, %15, "
        " %16, %17, %18, %19, %20, %21, %22, %23, "
        " %24, %25, %26, %27, %28, %29, %30, %31}, [%32];"
        : "=r"(r[0]),  "=r"(r[1]),  "=r"(r[2]),  "=r"(r[3]),
          "=r"(r[4]),  "=r"(r[5]),  "=r"(r[6]),  "=r"(r[7]),
          "=r"(r[8]),  "=r"(r[9]),  "=r"(r[10]), "=r"(r[11]),
          "=r"(r[12]), "=r"(r[13]), "=r"(r[14]), "=r"(r[15]),
          "=r"(r[16]), "=r"(r[17]), "=r"(r[18]), "=r"(r[19]),
          "=r"(r[20]), "=r"(r[21]), "=r"(r[22]), "=r"(r[23]),
          "=r"(r[24]), "=r"(r[25]), "=r"(r[26]), "=r"(r[27]),
          "=r"(r[28]), "=r"(r[29]), "=r"(r[30]), "=r"(r[31])
        : "r"(addr));
}
#else
// Fallback HMMA: warp-level mma.sync m16n8k16 bf16 -> fp32 (sm_80+, base target OK)
__device__ __forceinline__ void mma_bf16(float* d, const unsigned* a, const unsigned* b) {
    asm volatile(
        "mma.sync.aligned.m16n8k16.row.col.f32.bf16.bf16.f32 "
        "{%0,%1,%2,%3}, {%4,%5,%6,%7}, {%8,%9}, {%0,%1,%2,%3};"
        : "+f"(d[0]), "+f"(d[1]), "+f"(d[2]), "+f"(d[3])
        : "r"(a[0]), "r"(a[1]), "r"(a[2]), "r"(a[3]), "r"(b[0]), "r"(b[1]));
}
#endif

// ---------------------------------------------------------------------------
// Prep kernels: fp32 -> bf16 hi/lo decomposition (+ layout transforms)
// ---------------------------------------------------------------------------
__device__ __forceinline__ void split_bf16(float x, __nv_bfloat16& h, __nv_bfloat16& l) {
    h = __float2bfloat16(x);
    l = __float2bfloat16(x - __bfloat162float(h));
}

__global__ void prep_act(const float* __restrict__ src,
                         __nv_bfloat16* __restrict__ dhi,
                         __nv_bfloat16* __restrict__ dlo, int CIN) {
    __shared__ float t[32][33];
    const int b = blockIdx.z, ct = blockIdx.y * 32, pt = blockIdx.x * 32;
    const int tx = threadIdx.x, ty = threadIdx.y;
    for (int i = ty; i < 32; i += 8)
        t[i][tx] = src[((size_t)(b * CIN + ct + i)) * HW_ + pt + tx];
    __syncthreads();
    for (int i = ty; i < 32; i += 8) {
        float x = t[tx][i];
        __nv_bfloat16 h, l;
        split_bf16(x, h, l);
        size_t o = ((size_t)(b * HW_ + pt + i)) * CIN + ct + tx;
        dhi[o] = h;
        dlo[o] = l;
    }
}

__global__ void prep_wconv(const float* __restrict__ W,
                           __nv_bfloat16* __restrict__ dhi,
                           __nv_bfloat16* __restrict__ dlo, int M, int CIN) {
    int idx = blockIdx.x * 256 + threadIdx.x;
    if (idx >= M * CIN) return;
#pragma unroll
    for (int tap = 0; tap < 9; tap++) {
        float x = W[(size_t)idx * 9 + tap];
        __nv_bfloat16 h, l;
        split_bf16(x, h, l);
        size_t o = (size_t)tap * M * CIN + idx;
        dhi[o] = h;
        dlo[o] = l;
    }
}

__global__ void prep_wlin(const float* __restrict__ W,
                          __nv_bfloat16* __restrict__ dhi,
                          __nv_bfloat16* __restrict__ dlo, int n) {
    int i = blockIdx.x * 256 + threadIdx.x;
    if (i >= n) return;
    __nv_bfloat16 h, l;
    split_bf16(W[i], h, l);
    dhi[i] = h;
    dlo[i] = l;
}

__global__ void prep_biasqk(const float* __restrict__ qb, const float* __restrict__ kb,
                            float* __restrict__ dst) {
    int i = threadIdx.x;
    dst[i] = (i < 64) ? qb[i] : kb[i - 64];
}

// ---------------------------------------------------------------------------
// Implicit-conv GEMM (bf16-split, 3 MMA chains, fp32 accumulate)
//   D[m, pixel] = sum_{tap,c} W[tap][m][c] * X_nhwc[shift(pixel,tap)][c]
// Primary: tcgen05 SS (SW128 smem, TMEM accumulators, mbarrier pipeline).
// Fallback: warp-level mma.sync bf16 from the same swizzled smem tiles.
// ---------------------------------------------------------------------------
template<int CIN, int TAPS, int M_ATOMS, int EPI>
__global__ void __launch_bounds__(256, 1)
mma_conv(const __nv_bfloat16* __restrict__ Whi, const __nv_bfloat16* __restrict__ Wlo,
         const __nv_bfloat16* __restrict__ Xhi, const __nv_bfloat16* __restrict__ Xlo,
         const float* __restrict__ e0, const float* __restrict__ e1,
         const float* __restrict__ e2, const float* __restrict__ e3,
         float* __restrict__ Y, int Mtot)
{
    constexpr int M_ROWS  = 128 * M_ATOMS;
    constexpr int A_BYTES = M_ROWS * 128;
    constexpr int B_BYTES = 128 * 128;
    constexpr int STAGE   = 2 * A_BYTES + 2 * B_BYTES;
    constexpr int NCHUNK  = TAPS * (CIN / 64);

    extern __shared__ char dyn_smem[];
    char* sm = (char*)((((uintptr_t)dyn_smem) + 1023) & ~(uintptr_t)1023);

    const int tid = threadIdx.x;
    const int wid = tid >> 5;
    const int lane = tid & 31;

    const int m_base = blockIdx.x * M_ROWS;
    const int n_base = blockIdx.y * 128;
    const int bb  = n_base >> 12;
    const int sp0 = n_base & 4095;

#if HAS_TC
    constexpr unsigned IDESC =
        (1u << 4) | (1u << 7) | (1u << 10) | (16u << 17) | (8u << 24);
    __shared__ __align__(8) unsigned long long s_mbar[2];
    __shared__ unsigned s_tmem[1];
    const unsigned sbase = smem_u32(sm);
    if (wid == 0) tmem_alloc(smem_u32(&s_tmem[0]), 256);
    if (tid == 0) { mbar_init(smem_u32(&s_mbar[0]), 1); mbar_init(smem_u32(&s_mbar[1]), 1); }
    __syncthreads();
    unsigned tmem;
    asm volatile("ld.shared.b32 %0, [%1];" : "=r"(tmem) : "r"(smem_u32(&s_tmem[0])));
    const unsigned mbar[2] = { smem_u32(&s_mbar[0]), smem_u32(&s_mbar[1]) };
    int ph[2] = {0, 0};
#else
    // fallback warp tiling: warps = NWM x NWN, each warp 64 x WN output
    constexpr int NWM = M_ROWS / 64;
    constexpr int NWN = 8 / NWM;
    constexpr int WN  = 128 / NWN;
    const int wm = wid % NWM, wn = wid / NWM;
    const int g = lane >> 2, t = lane & 3;
    float acc[4][WN / 8][4];
#pragma unroll
    for (int i = 0; i < 4; i++)
#pragma unroll
        for (int j = 0; j < WN / 8; j++)
#pragma unroll
            for (int r = 0; r < 4; r++) acc[i][j][r] = 0.f;
#endif

    for (int chunk = 0; chunk < NCHUNK; ++chunk) {
        const int s   = chunk & 1;
        const int tap = (TAPS == 1) ? 0 : chunk / (CIN / 64);
        const int cb  = (TAPS == 1) ? chunk * 64 : (chunk % (CIN / 64)) * 64;
        const int dh  = (TAPS == 9) ? (tap / 3 - 1) : 0;
        const int dw  = (TAPS == 9) ? (tap % 3 - 1) : 0;

#if HAS_TC
        if (chunk >= 2) { mbar_wait(mbar[s], ph[s]); ph[s] ^= 1; }
#endif
        char* aHi = sm + s * STAGE;
        char* aLo = aHi + A_BYTES;
        char* bHi = aLo + A_BYTES;
        char* bLo = bHi + B_BYTES;

        // --- A (weights) tile: M_ROWS x 64 bf16 ---
        {
            const __nv_bfloat16* srcH = Whi + ((size_t)tap * Mtot + m_base) * CIN + cb;
            const __nv_bfloat16* srcL = Wlo + ((size_t)tap * Mtot + m_base) * CIN + cb;
#pragma unroll
            for (int u = 0; u < M_ROWS * 8 / 256; ++u) {
                int l = u * 256 + tid;
                int row = l >> 3, c16 = l & 7;
                size_t go = (size_t)row * CIN + c16 * 8;
                unsigned so = SW128((unsigned)(row * 128 + c16 * 16));
                *(uint4*)(aHi + so) = *(const uint4*)(srcH + go);
                *(uint4*)(aLo + so) = *(const uint4*)(srcL + go);
            }
        }
        // --- B (activations) tile: 128 pixels x 64 bf16, tap-shifted, zero-padded ---
        {
#pragma unroll
            for (int u = 0; u < 4; ++u) {
                int l = u * 256 + tid;
                int row = l >> 3, c16 = l & 7;
                int sp = sp0 + row;
                int h = (sp >> 6) + dh, w = (sp & 63) + dw;
                uint4 vh = make_uint4(0, 0, 0, 0), vl = make_uint4(0, 0, 0, 0);
                if ((unsigned)h < 64u && (unsigned)w < 64u) {
                    size_t go = ((size_t)(bb * HW_ + h * 64 + w)) * CIN + cb + c16 * 8;
                    vh = *(const uint4*)(Xhi + go);
                    vl = *(const uint4*)(Xlo + go);
                }
                unsigned so = SW128((unsigned)(row * 128 + c16 * 16));
                *(uint4*)(bHi + so) = vh;
                *(uint4*)(bLo + so) = vl;
            }
        }

#if HAS_TC
        fence_async_shared();
        __syncthreads();
        if (wid == 0 && elect_one()) {
            unsigned long long dAh = make_desc(sbase + s * STAGE);
            unsigned long long dAl = dAh + (A_BYTES >> 4);
            unsigned long long dBh = make_desc(sbase + s * STAGE + 2 * A_BYTES);
            unsigned long long dBl = dBh + (B_BYTES >> 4);
#pragma unroll
            for (int a = 0; a < M_ATOMS; ++a) {
                unsigned d = tmem + a * 128;
                unsigned long long ah = dAh + a * 1024;
                unsigned long long al = dAl + a * 1024;
#pragma unroll
                for (int kk = 0; kk < 4; ++kk) {
                    unsigned en0 = (chunk > 0 || kk > 0) ? 1u : 0u;
                    mma_ss_bf16(d, ah + kk * 2, dBh + kk * 2, IDESC, en0);
                    mma_ss_bf16(d, ah + kk * 2, dBl + kk * 2, IDESC, 1u);
                    mma_ss_bf16(d, al + kk * 2, dBh + kk * 2, IDESC, 1u);
                }
            }
            tc_commit(mbar[s]);
        }
#else
        __syncthreads();
        // warp-level HMMA over the swizzled tiles
#pragma unroll
        for (int kk = 0; kk < 4; ++kk) {
            const int kbyte = kk * 32 + t * 4;
            unsigned Ah[4][4], Al[4][4];
#pragma unroll
            for (int i = 0; i < 4; i++) {
                int r0 = wm * 64 + i * 16;
                Ah[i][0] = *(unsigned*)(aHi + SW128((r0 + g) * 128 + kbyte));
                Ah[i][1] = *(unsigned*)(aHi + SW128((r0 + g + 8) * 128 + kbyte));
                Ah[i][2] = *(unsigned*)(aHi + SW128((r0 + g) * 128 + kbyte + 16));
                Ah[i][3] = *(unsigned*)(aHi + SW128((r0 + g + 8) * 128 + kbyte + 16));
                Al[i][0] = *(unsigned*)(aLo + SW128((r0 + g) * 128 + kbyte));
                Al[i][1] = *(unsigned*)(aLo + SW128((r0 + g + 8) * 128 + kbyte));
                Al[i][2] = *(unsigned*)(aLo + SW128((r0 + g) * 128 + kbyte + 16));
                Al[i][3] = *(unsigned*)(aLo + SW128((r0 + g + 8) * 128 + kbyte + 16));
            }
#pragma unroll
            for (int j = 0; j < WN / 8; j++) {
                int n0 = wn * WN + j * 8 + g;
                unsigned Bh[2], Bl[2];
                Bh[0] = *(unsigned*)(bHi + SW128(n0 * 128 + kbyte));
                Bh[1] = *(unsigned*)(bHi + SW128(n0 * 128 + kbyte + 16));
                Bl[0] = *(unsigned*)(bLo + SW128(n0 * 128 + kbyte));
                Bl[1] = *(unsigned*)(bLo + SW128(n0 * 128 + kbyte + 16));
#pragma unroll
                for (int i = 0; i < 4; i++) {
                    mma_bf16(acc[i][j], Ah[i], Bh);
                    mma_bf16(acc[i][j], Ah[i], Bl);
                    mma_bf16(acc[i][j], Al[i], Bh);
                }
            }
        }
#endif
    }

#if HAS_TC
    {
        int c0 = NCHUNK - 2, c1 = NCHUNK - 1;
        int s0 = c0 & 1, s1 = c1 & 1;
        mbar_wait(mbar[s0], ph[s0]); ph[s0] ^= 1;
        mbar_wait(mbar[s1], ph[s1]); ph[s1] ^= 1;
    }
    tc_fence_after();

    // epilogue: TMEM -> BN/bias(+ReLU) -> gmem NCHW fp32
    const int a = tid >> 7;
    if (M_ATOMS == 2 || a == 0) {
        const int warp_in = (tid >> 5) & 3;
        const int mg = m_base + a * 128 + warp_in * 32 + lane;
        float sc, sh;
        if (EPI == 1) {
            float tt = e0[mg] * rsqrtf(e3[mg] + 1e-5f);
            sc = tt;
            sh = e1[mg] - e2[mg] * tt;
        } else {
            sc = 1.f;
            sh = e0[mg];
        }
        float* yrow = Y + ((size_t)(bb * Mtot + mg)) * HW_ + sp0;
#pragma unroll
        for (int cb4 = 0; cb4 < 4; ++cb4) {
            unsigned r[32];
            tmem_ld32(r, tmem + a * 128 + cb4 * 32);
            tc_wait_ld();
#pragma unroll
            for (int j = 0; j < 32; j += 4) {
                float4 v;
                v.x = fmaf(__uint_as_float(r[j + 0]), sc, sh);
                v.y = fmaf(__uint_as_float(r[j + 1]), sc, sh);
                v.z = fmaf(__uint_as_float(r[j + 2]), sc, sh);
                v.w = fmaf(__uint_as_float(r[j + 3]), sc, sh);
                if (EPI == 1) {
                    v.x = fmaxf(v.x, 0.f); v.y = fmaxf(v.y, 0.f);
                    v.z = fmaxf(v.z, 0.f); v.w = fmaxf(v.w, 0.f);
                }
                *(float4*)(yrow + cb4 * 32 + j) = v;
            }
        }
    }
    __syncthreads();
    if (wid == 0) tmem_dealloc(tmem, 256);
#else
    // fallback epilogue: registers -> BN/bias(+ReLU) -> gmem
#pragma unroll
    for (int i = 0; i < 4; i++) {
        int mr0 = m_base + wm * 64 + i * 16;
#pragma unroll
        for (int half = 0; half < 2; half++) {
            int mg = mr0 + g + half * 8;
            float sc, sh;
            if (EPI == 1) {
                float tt = e0[mg] * rsqrtf(e3[mg] + 1e-5f);
                sc = tt;
                sh = e1[mg] - e2[mg] * tt;
            } else {
                sc = 1.f;
                sh = e0[mg];
            }
            float* yrow = Y + ((size_t)(bb * Mtot + mg)) * HW_ + sp0;
#pragma unroll
            for (int j = 0; j < WN / 8; j++) {
                float v0 = fmaf(acc[i][j][half * 2 + 0], sc, sh);
                float v1 = fmaf(acc[i][j][half * 2 + 1], sc, sh);
                if (EPI == 1) { v0 = fmaxf(v0, 0.f); v1 = fmaxf(v1, 0.f); }
                *(float2*)(yrow + wn * WN + j * 8 + t * 2) = make_float2(v0, v1);
            }
        }
    }
#endif
}

// ---------------------------------------------------------------------------
// CCA kernels (fp32; proven in R1)
// ---------------------------------------------------------------------------
__global__ void __launch_bounds__(256) energyH_kernel(
    const float* __restrict__ qk, float* __restrict__ attn)
{
    const int w = blockIdx.x, b = blockIdx.y;
    __shared__ float Qs[64][65];
    __shared__ float Ks[64][65];
    const int tid = threadIdx.x;
    for (int l = tid; l < 4096; l += 256) {
        int c = l >> 6, h = l & 63;
        Qs[c][h] = qk[((size_t)(b * 128 + c)) * HW_ + h * 64 + w];
        Ks[c][h] = qk[((size_t)(b * 128 + 64 + c)) * HW_ + h * 64 + w];
    }
    __syncthreads();
    const int hh = tid & 63, ig = tid >> 6;
    float acc[16];
#pragma unroll
    for (int i = 0; i < 16; i++) acc[i] = 0.f;
    for (int c = 0; c < 64; c++) {
        float qv = Qs[c][hh];
#pragma unroll
        for (int i = 0; i < 16; i++) acc[i] += qv * Ks[c][ig * 16 + i];
    }
    float* orow = attn + (size_t)(((b * 64 + hh) * 64 + w)) * 128;
#pragma unroll
    for (int i = 0; i < 16; i++) {
        int ii = ig * 16 + i;
        orow[ii] = acc[i] + ((ii == hh) ? -1000000000.0f : 0.f);
    }
}

__global__ void __launch_bounds__(256) energyW_kernel(
    const float* __restrict__ qk, float* __restrict__ attn)
{
    const int h = blockIdx.x, b = blockIdx.y;
    __shared__ float Qs[64][65];
    __shared__ float Ks[64][65];
    const int tid = threadIdx.x;
    for (int l = tid; l < 4096; l += 256) {
        int c = l >> 6, w = l & 63;
        Qs[c][w] = qk[((size_t)(b * 128 + c)) * HW_ + h * 64 + w];
        Ks[c][w] = qk[((size_t)(b * 128 + 64 + c)) * HW_ + h * 64 + w];
    }
    __syncthreads();
    const int wq = tid & 63, jg = tid >> 6;
    float acc[16];
#pragma unroll
    for (int j = 0; j < 16; j++) acc[j] = 0.f;
    for (int c = 0; c < 64; c++) {
        float qv = Qs[c][wq];
#pragma unroll
        for (int j = 0; j < 16; j++) acc[j] += qv * Ks[c][jg * 16 + j];
    }
    float* orow = attn + (size_t)(((b * 64 + h) * 64 + wq)) * 128 + 64;
#pragma unroll
    for (int j = 0; j < 16; j++) orow[jg * 16 + j] = acc[j];
}

__global__ void __launch_bounds__(256) softmax_kernel(float* __restrict__ attn)
{
    int gw = (blockIdx.x * blockDim.x + threadIdx.x) >> 5;
    if (gw >= NPIX_) return;
    int lane = threadIdx.x & 31;
    float* row = attn + (size_t)gw * 128;
    float v0 = row[lane], v1 = row[lane + 32], v2 = row[lane + 64], v3 = row[lane + 96];
    float mx = fmaxf(fmaxf(v0, v1), fmaxf(v2, v3));
#pragma unroll
    for (int o = 16; o > 0; o >>= 1) mx = fmaxf(mx, __shfl_xor_sync(0xffffffffu, mx, o));
    v0 = expf(v0 - mx); v1 = expf(v1 - mx); v2 = expf(v2 - mx); v3 = expf(v3 - mx);
    float s = v0 + v1 + v2 + v3;
#pragma unroll
    for (int o = 16; o > 0; o >>= 1) s += __shfl_xor_sync(0xffffffffu, s, o);
    float inv = 1.0f / s;
    row[lane] = v0 * inv; row[lane + 32] = v1 * inv;
    row[lane + 64] = v2 * inv; row[lane + 96] = v3 * inv;
}

__global__ void __launch_bounds__(256) aggH_kernel(
    const float* __restrict__ v, const float* __restrict__ attn,
    const float* __restrict__ fin, float* __restrict__ fout,
    const float* __restrict__ gptr)
{
    const int w = blockIdx.x, b = blockIdx.y, cbk = blockIdx.z * 64;
    __shared__ float Vs[64][65];
    __shared__ float Am[64][65];
    const int tid = threadIdx.x;
    for (int l = tid; l < 4096; l += 256) {
        int c = l >> 6, i = l & 63;
        Vs[c][i] = v[(size_t)((b * 512 + cbk + c) * 64 + i) * 64 + w];
    }
    for (int l = tid; l < 4096; l += 256) {
        int h = l >> 6, i = l & 63;
        Am[h][i] = attn[(size_t)(((b * 64 + h) * 64 + w)) * 128 + i];
    }
    __syncthreads();
    const int tc = tid & 63, hg = tid >> 6;
    float acc[16];
#pragma unroll
    for (int t = 0; t < 16; t++) acc[t] = 0.f;
    for (int i = 0; i < 64; i++) {
        float vv = Vs[tc][i];
#pragma unroll
        for (int t = 0; t < 16; t++) acc[t] += vv * Am[hg * 16 + t][i];
    }
    const float g = *gptr;
#pragma unroll
    for (int t = 0; t < 16; t++) {
        int h = hg * 16 + t;
        size_t idx = (size_t)((b * 512 + cbk + tc) * 64 + h) * 64 + w;
        fout[idx] = fin[idx] + g * acc[t];
    }
}

__global__ void __launch_bounds__(256) aggW_kernel(
    const float* __restrict__ v, const float* __restrict__ attn,
    float* __restrict__ fout, const float* __restrict__ gptr)
{
    const int h = blockIdx.x, b = blockIdx.y, cbk = blockIdx.z * 64;
    __shared__ float Vs[64][65];
    __shared__ float Am[64][65];
    const int tid = threadIdx.x;
    for (int l = tid; l < 4096; l += 256) {
        int c = l >> 6, j = l & 63;
        Vs[c][j] = v[(size_t)((b * 512 + cbk + c) * 64 + h) * 64 + j];
    }
    for (int l = tid; l < 4096; l += 256) {
        int w = l >> 6, j = l & 63;
        Am[w][j] = attn[(size_t)(((b * 64 + h) * 64 + w)) * 128 + 64 + j];
    }
    __syncthreads();
    const int tc = tid & 63, wg = tid >> 6;
    float acc[16];
#pragma unroll
    for (int t = 0; t < 16; t++) acc[t] = 0.f;
    for (int j = 0; j < 64; j++) {
        float vv = Vs[tc][j];
#pragma unroll
        for (int t = 0; t < 16; t++) acc[t] += vv * Am[wg * 16 + t][j];
    }
    const float g = *gptr;
#pragma unroll
    for (int t = 0; t < 16; t++) {
        int w = wg * 16 + t;
        size_t idx = (size_t)((b * 512 + cbk + tc) * 64 + h) * 64 + w;
        fout[idx] += g * acc[t];
    }
}

// ---------------------------------------------------------------------------
// Launch
// ---------------------------------------------------------------------------
extern "C" void kernel_launch(void* const* d_in, const int* in_sizes, int n_in,
                              void* d_out, int out_size)
{
    const float* x     = (const float*)d_in[0];
    const float* c1w   = (const float*)d_in[1];
    const float* bn1g  = (const float*)d_in[2];
    const float* bn1b  = (const float*)d_in[3];
    const float* bn1m  = (const float*)d_in[4];
    const float* bn1v  = (const float*)d_in[5];
    const float* qw    = (const float*)d_in[6];
    const float* qb    = (const float*)d_in[7];
    const float* kw    = (const float*)d_in[8];
    const float* kb    = (const float*)d_in[9];
    const float* vw    = (const float*)d_in[10];
    const float* vb    = (const float*)d_in[11];
    const float* gamma = (const float*)d_in[12];
    const float* c2w   = (const float*)d_in[13];
    const float* bn2g  = (const float*)d_in[14];
    const float* bn2b  = (const float*)d_in[15];
    const float* bn2m  = (const float*)d_in[16];
    const float* bn2v  = (const float*)d_in[17];
    float* out = (float*)d_out;

    float *fA, *fB, *gv, *gqk, *gat, *gbqk;
    __nv_bfloat16 *xhi, *xlo, *fhi, *flo, *w1hi, *w1lo, *w2hi, *w2lo, *wqkhi, *wqklo, *wvhi, *wvlo;
    cudaGetSymbolAddress((void**)&fA, g_featsA);
    cudaGetSymbolAddress((void**)&fB, g_featsB);
    cudaGetSymbolAddress((void**)&gv, g_v);
    cudaGetSymbolAddress((void**)&gqk, g_qk);
    cudaGetSymbolAddress((void**)&gat, g_attn);
    cudaGetSymbolAddress((void**)&gbqk, g_bqk);
    cudaGetSymbolAddress((void**)&xhi, g_xhi);
    cudaGetSymbolAddress((void**)&xlo, g_xlo);
    cudaGetSymbolAddress((void**)&fhi, g_fhi);
    cudaGetSymbolAddress((void**)&flo, g_flo);
    cudaGetSymbolAddress((void**)&w1hi, g_w1hi);
    cudaGetSymbolAddress((void**)&w1lo, g_w1lo);
    cudaGetSymbolAddress((void**)&w2hi, g_w2hi);
    cudaGetSymbolAddress((void**)&w2lo, g_w2lo);
    cudaGetSymbolAddress((void**)&wqkhi, g_wqkhi);
    cudaGetSymbolAddress((void**)&wqklo, g_wqklo);
    cudaGetSymbolAddress((void**)&wvhi, g_wvhi);
    cudaGetSymbolAddress((void**)&wvlo, g_wvlo);

    const int SMEM2 = 2 * (2 * 2 * 128 * 128 + 2 * 128 * 128) + 1024;  // 197632
    const int SMEM1 = 2 * (2 * 128 * 128 + 2 * 128 * 128) + 1024;      // 132096
    cudaFuncSetAttribute(mma_conv<2048, 9, 2, 1>, cudaFuncAttributeMaxDynamicSharedMemorySize, SMEM2);
    cudaFuncSetAttribute(mma_conv<512, 9, 2, 1>,  cudaFuncAttributeMaxDynamicSharedMemorySize, SMEM2);
    cudaFuncSetAttribute(mma_conv<512, 1, 2, 0>,  cudaFuncAttributeMaxDynamicSharedMemorySize, SMEM2);
    cudaFuncSetAttribute(mma_conv<512, 1, 1, 0>,  cudaFuncAttributeMaxDynamicSharedMemorySize, SMEM1);

    // --- weight / bias prep ---
    prep_wconv<<<(512 * 2048 + 255) / 256, 256>>>(c1w, w1hi, w1lo, 512, 2048);
    prep_wconv<<<(512 * 512 + 255) / 256, 256>>>(c2w, w2hi, w2lo, 512, 512);
    prep_wlin<<<(64 * 512 + 255) / 256, 256>>>(qw, wqkhi, wqklo, 64 * 512);
    prep_wlin<<<(64 * 512 + 255) / 256, 256>>>(kw, wqkhi + 64 * 512, wqklo + 64 * 512, 64 * 512);
    prep_wlin<<<(512 * 512 + 255) / 256, 256>>>(vw, wvhi, wvlo, 512 * 512);
    prep_biasqk<<<1, 128>>>(qb, kb, gbqk);

    // --- conv1 + BN + ReLU ---
    prep_act<<<dim3(128, 64, 4), dim3(32, 8)>>>(x, xhi, xlo, 2048);
    mma_conv<2048, 9, 2, 1><<<dim3(2, 128), 256, SMEM2>>>(
        w1hi, w1lo, xhi, xlo, bn1g, bn1b, bn1m, bn1v, fA, 512);

    // --- 2x criss-cross attention ---
    float* cur = fA;
    float* nxt = fB;
    for (int it = 0; it < 2; ++it) {
        prep_act<<<dim3(128, 16, 4), dim3(32, 8)>>>(cur, fhi, flo, 512);
        mma_conv<512, 1, 1, 0><<<dim3(1, 128), 256, SMEM1>>>(
            wqkhi, wqklo, fhi, flo, gbqk, nullptr, nullptr, nullptr, gqk, 128);
        mma_conv<512, 1, 2, 0><<<dim3(2, 128), 256, SMEM2>>>(
            wvhi, wvlo, fhi, flo, vb, nullptr, nullptr, nullptr, gv, 512);
        energyH_kernel<<<dim3(64, 4), 256>>>(gqk, gat);
        energyW_kernel<<<dim3(64, 4), 256>>>(gqk, gat);
        softmax_kernel<<<NPIX_ / 8, 256>>>(gat);
        aggH_kernel<<<dim3(64, 4, 8), 256>>>(gv, gat, cur, nxt, gamma);
        aggW_kernel<<<dim3(64, 4, 8), 256>>>(gv, gat, nxt, gamma);
        float* tmp = cur; cur = nxt; nxt = tmp;
    }

    // --- conv2 + BN + ReLU ---
    prep_act<<<dim3(128, 16, 4), dim3(32, 8)>>>(cur, fhi, flo, 512);
    mma_conv<512, 9, 2, 1><<<dim3(2, 128), 256, SMEM2>>>(
        w2hi, w2lo, fhi, flo, bn2g, bn2b, bn2m, bn2v, out, 512);
}

// round 4
// speedup vs baseline: 8.2945x; 1.2971x over previous
#include <cuda_runtime.h>
#include <cuda_bf16.h>
#include <math.h>
#include <stdint.h>

#define HW_   4096
#define NPIX_ 16384

// tcgen05 exists only in the arch-specific (sm_103a/sm_100a) pass.
#if defined(__CUDA_ARCH__) && (defined(__CUDA_ARCH_FEAT_SM103_ALL) || defined(__CUDA_ARCH_FEAT_SM100_ALL))
#define HAS_TC 1
#else
#define HAS_TC 0
#endif

// ---------------------------------------------------------------------------
// Scratch (device globals; allocation is forbidden)
// ---------------------------------------------------------------------------
__device__ float g_featsA[4 * 512 * 4096];
__device__ float g_featsB[4 * 512 * 4096];
__device__ float g_v[4 * 512 * 4096];
__device__ float g_qk[4 * 128 * 4096];
__device__ float g_attn[4 * 4096 * 128];
__device__ float g_bqk[128];
__device__ __nv_bfloat16 g_xhi[4 * 4096 * 2048];
__device__ __nv_bfloat16 g_xlo[4 * 4096 * 2048];
__device__ __nv_bfloat16 g_fhi[4 * 4096 * 512];
__device__ __nv_bfloat16 g_flo[4 * 4096 * 512];
__device__ __nv_bfloat16 g_w1hi[9 * 512 * 2048];
__device__ __nv_bfloat16 g_w1lo[9 * 512 * 2048];
__device__ __nv_bfloat16 g_w2hi[9 * 512 * 512];
__device__ __nv_bfloat16 g_w2lo[9 * 512 * 512];
__device__ __nv_bfloat16 g_wqkhi[128 * 512];
__device__ __nv_bfloat16 g_wqklo[128 * 512];
__device__ __nv_bfloat16 g_wvhi[512 * 512];
__device__ __nv_bfloat16 g_wvlo[512 * 512];

// ---------------------------------------------------------------------------
// Generic helpers (valid on base sm_103)
// ---------------------------------------------------------------------------
__device__ __forceinline__ unsigned smem_u32(const void* p) {
    unsigned a;
    asm("{ .reg .u64 t; cvta.to.shared.u64 t, %1; cvt.u32.u64 %0, t; }"
        : "=r"(a) : "l"(p));
    return a;
}
__device__ __forceinline__ unsigned elect_one() {
    unsigned p;
    asm volatile("{ .reg .pred p; elect.sync _|p, 0xFFFFFFFF; selp.b32 %0, 1, 0, p; }"
                 : "=r"(p));
    return p;
}
#define SW128(o) ((o) ^ (((o) >> 3) & 0x70))
__device__ __forceinline__ void mbar_init(unsigned mbar, unsigned cnt) {
    asm volatile("mbarrier.init.shared.b64 [%0], %1;" :: "r"(mbar), "r"(cnt) : "memory");
}
__device__ __forceinline__ void mbar_wait(unsigned mbar, unsigned phase) {
    asm volatile(
        "{\n\t.reg .pred P;\n\t"
        "WL_%=:\n\t"
        "mbarrier.try_wait.parity.acquire.cta.shared::cta.b64 P, [%0], %1, 0x989680;\n\t"
        "@P bra.uni WD_%=;\n\t"
        "bra.uni WL_%=;\n\t"
        "WD_%=:\n\t}"
        :: "r"(mbar), "r"(phase) : "memory");
}
__device__ __forceinline__ void fence_async_shared() {
    asm volatile("fence.proxy.async;" ::: "memory");
}

// ---------------------------------------------------------------------------
// tcgen05 / cluster helpers (arch-specific pass only)
// ---------------------------------------------------------------------------
#if HAS_TC
static constexpr unsigned long long SMEM_DESC_BASE_SW128 =
    (2ull << 61) | (1ull << 46) | (64ull << 32) | (1ull << 16);
__device__ __forceinline__ unsigned long long make_desc(unsigned addr) {
    return SMEM_DESC_BASE_SW128 | ((unsigned long long)(addr >> 4) & 0x3FFFull);
}
__device__ __forceinline__ void mbar_wait_cluster(unsigned mbar, unsigned phase) {
    asm volatile(
        "{\n\t.reg .pred P;\n\t"
        "WL_%=:\n\t"
        "mbarrier.try_wait.parity.acquire.cluster.shared::cta.b64 P, [%0], %1, 0x989680;\n\t"
        "@P bra.uni WD_%=;\n\t"
        "bra.uni WL_%=;\n\t"
        "WD_%=:\n\t}"
        :: "r"(mbar), "r"(phase) : "memory");
}
__device__ __forceinline__ void mbar_arrive_rank0(unsigned local_addr) {
    asm volatile(
        "{\n\t.reg .b32 r;\n\t"
        "mapa.shared::cluster.u32 r, %0, 0;\n\t"
        "mbarrier.arrive.shared::cluster.b64 _, [r];\n\t}"
        :: "r"(local_addr) : "memory");
}
__device__ __forceinline__ void cluster_sync_() {
    asm volatile("barrier.cluster.arrive.aligned;" ::: "memory");
    asm volatile("barrier.cluster.wait.aligned;" ::: "memory");
}
__device__ __forceinline__ void tmem_alloc_cg1(unsigned dst_smem, unsigned ncols) {
    asm volatile("tcgen05.alloc.cta_group::1.sync.aligned.shared::cta.b32 [%0], %1;"
                 :: "r"(dst_smem), "r"(ncols) : "memory");
}
__device__ __forceinline__ void tmem_dealloc_cg1(unsigned tmem, unsigned ncols) {
    asm volatile("tcgen05.dealloc.cta_group::1.sync.aligned.b32 %0, %1;"
                 :: "r"(tmem), "r"(ncols));
}
__device__ __forceinline__ void tmem_alloc_cg2(unsigned dst_smem, unsigned ncols) {
    asm volatile("tcgen05.alloc.cta_group::2.sync.aligned.shared::cta.b32 [%0], %1;"
                 :: "r"(dst_smem), "r"(ncols) : "memory");
}
__device__ __forceinline__ void tmem_dealloc_cg2(unsigned tmem, unsigned ncols) {
    asm volatile("tcgen05.dealloc.cta_group::2.sync.aligned.b32 %0, %1;"
                 :: "r"(tmem), "r"(ncols));
}
__device__ __forceinline__ void tc_relinquish_cg2() {
    asm volatile("tcgen05.relinquish_alloc_permit.cta_group::2.sync.aligned;");
}
__device__ __forceinline__ void tc_commit_cg1(unsigned mbar) {
    asm volatile("tcgen05.commit.cta_group::1.mbarrier::arrive::one.shared::cluster.b64 [%0];"
                 :: "r"(mbar) : "memory");
}
__device__ __forceinline__ void tc_commit_mc_cg2(unsigned mbar, unsigned short mask) {
    asm volatile("tcgen05.commit.cta_group::2.mbarrier::arrive::one.shared::cluster.multicast::cluster.b64 [%0], %1;"
                 :: "r"(mbar), "h"(mask) : "memory");
}
__device__ __forceinline__ void tc_fence_after() {
    asm volatile("tcgen05.fence::after_thread_sync;" ::: "memory");
}
__device__ __forceinline__ void tc_wait_ld() {
    asm volatile("tcgen05.wait::ld.sync.aligned;" ::: "memory");
}
__device__ __forceinline__ void mma_cg1(unsigned d, unsigned long long ad,
                                        unsigned long long bd, unsigned idesc, unsigned en) {
    asm volatile(
        "{\n\t.reg .pred p;\n\tsetp.ne.u32 p, %4, 0;\n\t"
        "tcgen05.mma.cta_group::1.kind::f16 [%0], %1, %2, %3, {%5, %5, %5, %5}, p;\n\t}"
        :: "r"(d), "l"(ad), "l"(bd), "r"(idesc), "r"(en), "r"(0u) : "memory");
}
__device__ __forceinline__ void mma_cg2(unsigned d, unsigned long long ad,
                                        unsigned long long bd, unsigned idesc, unsigned en) {
    asm volatile(
        "{\n\t.reg .pred p;\n\tsetp.ne.u32 p, %4, 0;\n\t"
        "tcgen05.mma.cta_group::2.kind::f16 [%0], %1, %2, %3, "
        "{%5, %5, %5, %5, %5, %5, %5, %5}, p;\n\t}"
        :: "r"(d), "l"(ad), "l"(bd), "r"(idesc), "r"(en), "r"(0u) : "memory");
}
__device__ __forceinline__ void tmem_ld32(unsigned* r, unsigned addr) {
    asm volatile(
        "tcgen05.ld.sync.aligned.32x32b.x32.b32 "
        "{%0, %1, %2, %3, %4, %5, %6, %7, "
        " %8, %9, %10, %11, %12, %13, %14, %15, "
        " %16, %17, %18, %19, %20, %21, %22, %23, "
        " %24, %25, %26, %27, %28, %29, %30, %31}, [%32];"
        : "=r"(r[0]),  "=r"(r[1]),  "=r"(r[2]),  "=r"(r[3]),
          "=r"(r[4]),  "=r"(r[5]),  "=r"(r[6]),  "=r"(r[7]),
          "=r"(r[8]),  "=r"(r[9]),  "=r"(r[10]), "=r"(r[11]),
          "=r"(r[12]), "=r"(r[13]), "=r"(r[14]), "=r"(r[15]),
          "=r"(r[16]), "=r"(r[17]), "=r"(r[18]), "=r"(r[19]),
          "=r"(r[20]), "=r"(r[21]), "=r"(r[22]), "=r"(r[23]),
          "=r"(r[24]), "=r"(r[25]), "=r"(r[26]), "=r"(r[27]),
          "=r"(r[28]), "=r"(r[29]), "=r"(r[30]), "=r"(r[31])
        : "r"(addr));
}
__device__ __forceinline__ void cp16(unsigned dst, const void* src, unsigned bytes) {
    asm volatile("cp.async.cg.shared.global [%0], [%1], 16, %2;"
                 :: "r"(dst), "l"(src), "r"(bytes) : "memory");
}
__device__ __forceinline__ void cp_commit_wait0() {
    asm volatile("cp.async.commit_group;" ::: "memory");
    asm volatile("cp.async.wait_group 0;" ::: "memory");
}
#endif

// ---------------------------------------------------------------------------
// Prep kernels: fp32 -> bf16 hi/lo decomposition (+ layout transforms)
// ---------------------------------------------------------------------------
__device__ __forceinline__ void split_bf16(float x, __nv_bfloat16& h, __nv_bfloat16& l) {
    h = __float2bfloat16(x);
    l = __float2bfloat16(x - __bfloat162float(h));
}

__global__ void prep_act(const float* __restrict__ src,
                         __nv_bfloat16* __restrict__ dhi,
                         __nv_bfloat16* __restrict__ dlo, int CIN) {
    __shared__ float t[32][33];
    const int b = blockIdx.z, ct = blockIdx.y * 32, pt = blockIdx.x * 32;
    const int tx = threadIdx.x, ty = threadIdx.y;
    for (int i = ty; i < 32; i += 8)
        t[i][tx] = src[((size_t)(b * CIN + ct + i)) * HW_ + pt + tx];
    __syncthreads();
    for (int i = ty; i < 32; i += 8) {
        float x = t[tx][i];
        __nv_bfloat16 h, l;
        split_bf16(x, h, l);
        size_t o = ((size_t)(b * HW_ + pt + i)) * CIN + ct + tx;
        dhi[o] = h;
        dlo[o] = l;
    }
}

__global__ void prep_wconv(const float* __restrict__ W,
                           __nv_bfloat16* __restrict__ dhi,
                           __nv_bfloat16* __restrict__ dlo, int M, int CIN) {
    int idx = blockIdx.x * 256 + threadIdx.x;
    if (idx >= M * CIN) return;
#pragma unroll
    for (int tap = 0; tap < 9; tap++) {
        float x = W[(size_t)idx * 9 + tap];
        __nv_bfloat16 h, l;
        split_bf16(x, h, l);
        size_t o = (size_t)tap * M * CIN + idx;
        dhi[o] = h;
        dlo[o] = l;
    }
}

__global__ void prep_wlin(const float* __restrict__ W,
                          __nv_bfloat16* __restrict__ dhi,
                          __nv_bfloat16* __restrict__ dlo, int n) {
    int i = blockIdx.x * 256 + threadIdx.x;
    if (i >= n) return;
    __nv_bfloat16 h, l;
    split_bf16(W[i], h, l);
    dhi[i] = h;
    dlo[i] = l;
}

__global__ void prep_biasqk(const float* __restrict__ qb, const float* __restrict__ kb,
                            float* __restrict__ dst) {
    int i = threadIdx.x;
    dst[i] = (i < 64) ? qb[i] : kb[i - 64];
}

// ---------------------------------------------------------------------------
// cg2 implicit-conv GEMM: cluster of 2 CTAs, M=256 per cluster (128 per CTA),
// 4 n-tiles of 128 pixels (512 pixels per cluster), bf16-split 3-MMA chains.
// B split N/2 per CTA per cg2 semantics. cp.async loads with zfill padding.
// ---------------------------------------------------------------------------
template<int CIN, int TAPS, int EPI>
__global__ void __launch_bounds__(256, 1) __cluster_dims__(2, 1, 1)
mma_conv_cg2(const __nv_bfloat16* __restrict__ Whi, const __nv_bfloat16* __restrict__ Wlo,
             const __nv_bfloat16* __restrict__ Xhi, const __nv_bfloat16* __restrict__ Xlo,
             const float* __restrict__ e0, const float* __restrict__ e1,
             const float* __restrict__ e2, const float* __restrict__ e3,
             float* __restrict__ Y, int Mtot)
{
#if HAS_TC
    constexpr int NCHUNK = TAPS * (CIN / 64);
    constexpr int A_HI = 0;            // 128 rows x 128B
    constexpr int A_LO = 16384;
    constexpr int B_HI0 = 32768;       // 4 tiles x 64 rows x 128B
    constexpr int B_LO0 = 65536;
    constexpr int STAGE = 98304;       // 96 KB
    constexpr unsigned IDESC2 =
        (1u << 4) | (1u << 7) | (1u << 10) | (16u << 17) | (16u << 24); // f32, bf16, N=128, M=256

    extern __shared__ char dyn_smem[];
    __shared__ __align__(8) unsigned long long s_full[2];
    __shared__ __align__(8) unsigned long long s_done[2];
    __shared__ unsigned s_tmem[1];

    char* sm = (char*)((((uintptr_t)dyn_smem) + 1023) & ~(uintptr_t)1023);
    const unsigned sbase = smem_u32(sm);

    const int tid  = threadIdx.x;
    const int wid  = tid >> 5;
    const int lane = tid & 31;
    const unsigned rank = blockIdx.x & 1;
    const int m_base = (blockIdx.x >> 1) * 256;
    const int n_base = blockIdx.y * 512;
    const int bb   = n_base >> 12;
    const int sp00 = n_base & 4095;

    if (wid == 0) tmem_alloc_cg2(smem_u32(&s_tmem[0]), 512);
    if (tid == 0) {
        mbar_init(smem_u32(&s_full[0]), 2);
        mbar_init(smem_u32(&s_full[1]), 2);
        mbar_init(smem_u32(&s_done[0]), 1);
        mbar_init(smem_u32(&s_done[1]), 1);
    }
    __syncthreads();
    unsigned tmem;
    asm volatile("ld.shared.b32 %0, [%1];" : "=r"(tmem) : "r"(smem_u32(&s_tmem[0])));
    const unsigned fullb[2] = { smem_u32(&s_full[0]), smem_u32(&s_full[1]) };
    const unsigned doneb[2] = { smem_u32(&s_done[0]), smem_u32(&s_done[1]) };
    cluster_sync_();   // barriers initialized in both CTAs before any cross-CTA arrive

    int dph[2] = {0, 0};
    int fph[2] = {0, 0};

    for (int chunk = 0; chunk < NCHUNK; ++chunk) {
        const int s   = chunk & 1;
        const int tap = (TAPS == 1) ? 0 : chunk / (CIN / 64);
        const int cb  = (TAPS == 1) ? chunk * 64 : (chunk % (CIN / 64)) * 64;
        const int dh  = (TAPS == 9) ? (tap / 3 - 1) : 0;
        const int dw  = (TAPS == 9) ? (tap % 3 - 1) : 0;

        if (chunk >= 2) { mbar_wait(doneb[s], dph[s]); dph[s] ^= 1; }

        const unsigned stg = sbase + s * STAGE;

        // --- A: this CTA's 128 M-rows x 64 ch (hi+lo) ---
        {
            const __nv_bfloat16* srcH =
                Whi + ((size_t)tap * Mtot + m_base + rank * 128) * CIN + cb;
            const __nv_bfloat16* srcL =
                Wlo + ((size_t)tap * Mtot + m_base + rank * 128) * CIN + cb;
#pragma unroll
            for (int u = 0; u < 4; ++u) {
                int l = u * 256 + tid;
                int row = l >> 3, c16 = l & 7;
                size_t go = (size_t)row * CIN + c16 * 8;
                unsigned so = SW128((unsigned)(row * 128 + c16 * 16));
                cp16(stg + A_HI + so, srcH + go, 16);
                cp16(stg + A_LO + so, srcL + go, 16);
            }
        }
        // --- B: 4 n-tiles, this CTA's 64-row half of each, tap-shifted, zfill OOB ---
        {
#pragma unroll
            for (int u = 0; u < 8; ++u) {
                int l = u * 256 + tid;
                int t = l >> 9, r = (l >> 3) & 63, c16 = l & 7;
                int sp = sp00 + t * 128 + (int)rank * 64 + r;
                int h = (sp >> 6) + dh, w = (sp & 63) + dw;
                bool ok = ((unsigned)h < 64u) && ((unsigned)w < 64u);
                unsigned bytes = ok ? 16u : 0u;
                size_t go = ((size_t)(bb * HW_ + (ok ? h * 64 + w : 0))) * CIN + cb + c16 * 8;
                unsigned so = SW128((unsigned)(r * 128 + c16 * 16));
                cp16(stg + B_HI0 + t * 8192 + so, Xhi + go, bytes);
                cp16(stg + B_LO0 + t * 8192 + so, Xlo + go, bytes);
            }
        }
        cp_commit_wait0();
        __syncthreads();
        if (tid == 0) {
            fence_async_shared();
            mbar_arrive_rank0(fullb[s]);
        }
        if (rank == 0 && wid == 0 && elect_one()) {
            mbar_wait_cluster(fullb[s], fph[s]); fph[s] ^= 1;
            unsigned long long dAh = make_desc(stg + A_HI);
            unsigned long long dAl = make_desc(stg + A_LO);
#pragma unroll
            for (int t = 0; t < 4; ++t) {
                unsigned d = tmem + t * 128;
                unsigned long long dBh = make_desc(stg + B_HI0 + t * 8192);
                unsigned long long dBl = make_desc(stg + B_LO0 + t * 8192);
#pragma unroll
                for (int kk = 0; kk < 4; ++kk) {
                    unsigned en0 = (chunk > 0 || kk > 0) ? 1u : 0u;
                    mma_cg2(d, dAh + kk * 2, dBh + kk * 2, IDESC2, en0);
                    mma_cg2(d, dAh + kk * 2, dBl + kk * 2, IDESC2, 1u);
                    mma_cg2(d, dAl + kk * 2, dBh + kk * 2, IDESC2, 1u);
                }
            }
            tc_commit_mc_cg2(doneb[s], 0x3);
        }
    }

    // drain last two chunks
    {
        int s0 = (NCHUNK - 2) & 1, s1 = (NCHUNK - 1) & 1;
        mbar_wait(doneb[s0], dph[s0]); dph[s0] ^= 1;
        mbar_wait(doneb[s1], dph[s1]); dph[s1] ^= 1;
    }
    tc_fence_after();

    // --- epilogue: each CTA's TMEM holds its 128 M-rows x (4 tiles x 128 px) ---
    {
        const int wg = wid >> 2;                // 0: tiles 0-1, 1: tiles 2-3
        const int mg = m_base + (int)rank * 128 + (wid & 3) * 32 + lane;
        float sc, sh;
        if (EPI == 1) {
            float tt = e0[mg] * rsqrtf(e3[mg] + 1e-5f);
            sc = tt;
            sh = e1[mg] - e2[mg] * tt;
        } else {
            sc = 1.f;
            sh = e0[mg];
        }
        float* yrow = Y + ((size_t)(bb * Mtot + mg)) * HW_ + sp00;
#pragma unroll
        for (int ti = 0; ti < 2; ++ti) {
            int t = wg * 2 + ti;
#pragma unroll
            for (int cb4 = 0; cb4 < 4; ++cb4) {
                unsigned r[32];
                tmem_ld32(r, tmem + t * 128 + cb4 * 32);
                tc_wait_ld();
#pragma unroll
                for (int j = 0; j < 32; j += 4) {
                    float4 v;
                    v.x = fmaf(__uint_as_float(r[j + 0]), sc, sh);
                    v.y = fmaf(__uint_as_float(r[j + 1]), sc, sh);
                    v.z = fmaf(__uint_as_float(r[j + 2]), sc, sh);
                    v.w = fmaf(__uint_as_float(r[j + 3]), sc, sh);
                    if (EPI == 1) {
                        v.x = fmaxf(v.x, 0.f); v.y = fmaxf(v.y, 0.f);
                        v.z = fmaxf(v.z, 0.f); v.w = fmaxf(v.w, 0.f);
                    }
                    *(float4*)(yrow + t * 128 + cb4 * 32 + j) = v;
                }
            }
        }
    }
    __syncthreads();
    if (wid == 0) {
        tc_relinquish_cg2();
        tmem_dealloc_cg2(tmem, 512);
    }
    cluster_sync_();
#endif  // HAS_TC (non-a pass: empty body; sm_103a cubin is what the driver runs)
}

// ---------------------------------------------------------------------------
// cg1 GEMM for the small q/k projection (M=128), proven in R3.
// ---------------------------------------------------------------------------
template<int CIN, int EPI>
__global__ void __launch_bounds__(256, 1)
mma_proj_cg1(const __nv_bfloat16* __restrict__ Whi, const __nv_bfloat16* __restrict__ Wlo,
             const __nv_bfloat16* __restrict__ Xhi, const __nv_bfloat16* __restrict__ Xlo,
             const float* __restrict__ e0, float* __restrict__ Y, int Mtot)
{
#if HAS_TC
    constexpr int A_BYTES = 128 * 128;
    constexpr int B_BYTES = 128 * 128;
    constexpr int STAGE   = 2 * A_BYTES + 2 * B_BYTES;
    constexpr int NCHUNK  = CIN / 64;
    constexpr unsigned IDESC =
        (1u << 4) | (1u << 7) | (1u << 10) | (16u << 17) | (8u << 24);

    extern __shared__ char dyn_smem[];
    __shared__ __align__(8) unsigned long long s_mbar[2];
    __shared__ unsigned s_tmem[1];

    char* sm = (char*)((((uintptr_t)dyn_smem) + 1023) & ~(uintptr_t)1023);
    const unsigned sbase = smem_u32(sm);
    const int tid = threadIdx.x;
    const int wid = tid >> 5;
    const int lane = tid & 31;

    if (wid == 0) tmem_alloc_cg1(smem_u32(&s_tmem[0]), 256);
    if (tid == 0) { mbar_init(smem_u32(&s_mbar[0]), 1); mbar_init(smem_u32(&s_mbar[1]), 1); }
    __syncthreads();
    unsigned tmem;
    asm volatile("ld.shared.b32 %0, [%1];" : "=r"(tmem) : "r"(smem_u32(&s_tmem[0])));
    const unsigned mbar[2] = { smem_u32(&s_mbar[0]), smem_u32(&s_mbar[1]) };

    const int n_base = blockIdx.y * 128;
    const int bb  = n_base >> 12;
    const int sp0 = n_base & 4095;
    int ph[2] = {0, 0};

    for (int chunk = 0; chunk < NCHUNK; ++chunk) {
        const int s  = chunk & 1;
        const int cb = chunk * 64;
        if (chunk >= 2) { mbar_wait(mbar[s], ph[s]); ph[s] ^= 1; }

        char* aHi = sm + s * STAGE;
        char* aLo = aHi + A_BYTES;
        char* bHi = aLo + A_BYTES;
        char* bLo = bHi + B_BYTES;
#pragma unroll
        for (int u = 0; u < 4; ++u) {
            int l = u * 256 + tid;
            int row = l >> 3, c16 = l & 7;
            size_t go = (size_t)row * CIN + cb + c16 * 8;
            unsigned so = SW128((unsigned)(row * 128 + c16 * 16));
            *(uint4*)(aHi + so) = *(const uint4*)(Whi + go);
            *(uint4*)(aLo + so) = *(const uint4*)(Wlo + go);
        }
#pragma unroll
        for (int u = 0; u < 4; ++u) {
            int l = u * 256 + tid;
            int row = l >> 3, c16 = l & 7;
            size_t go = ((size_t)(bb * HW_ + sp0 + row)) * CIN + cb + c16 * 8;
            unsigned so = SW128((unsigned)(row * 128 + c16 * 16));
            *(uint4*)(bHi + so) = *(const uint4*)(Xhi + go);
            *(uint4*)(bLo + so) = *(const uint4*)(Xlo + go);
        }
        fence_async_shared();
        __syncthreads();

        if (wid == 0 && elect_one()) {
            unsigned long long dAh = make_desc(sbase + s * STAGE);
            unsigned long long dAl = dAh + (A_BYTES >> 4);
            unsigned long long dBh = make_desc(sbase + s * STAGE + 2 * A_BYTES);
            unsigned long long dBl = dBh + (B_BYTES >> 4);
#pragma unroll
            for (int kk = 0; kk < 4; ++kk) {
                unsigned en0 = (chunk > 0 || kk > 0) ? 1u : 0u;
                mma_cg1(tmem, dAh + kk * 2, dBh + kk * 2, IDESC, en0);
                mma_cg1(tmem, dAh + kk * 2, dBl + kk * 2, IDESC, 1u);
                mma_cg1(tmem, dAl + kk * 2, dBh + kk * 2, IDESC, 1u);
            }
            tc_commit_cg1(mbar[s]);
        }
    }
    {
        int s0 = (NCHUNK - 2) & 1, s1 = (NCHUNK - 1) & 1;
        mbar_wait(mbar[s0], ph[s0]); ph[s0] ^= 1;
        mbar_wait(mbar[s1], ph[s1]); ph[s1] ^= 1;
    }
    tc_fence_after();

    if (wid < 4) {
        const int mg = wid * 32 + lane;
        float sh = e0[mg];
        float* yrow = Y + ((size_t)(bb * Mtot + mg)) * HW_ + sp0;
#pragma unroll
        for (int cb4 = 0; cb4 < 4; ++cb4) {
            unsigned r[32];
            tmem_ld32(r, tmem + cb4 * 32);
            tc_wait_ld();
#pragma unroll
            for (int j = 0; j < 32; j += 4) {
                float4 v;
                v.x = __uint_as_float(r[j + 0]) + sh;
                v.y = __uint_as_float(r[j + 1]) + sh;
                v.z = __uint_as_float(r[j + 2]) + sh;
                v.w = __uint_as_float(r[j + 3]) + sh;
                *(float4*)(yrow + cb4 * 32 + j) = v;
            }
        }
    }
    __syncthreads();
    if (wid == 0) tmem_dealloc_cg1(tmem, 256);
#endif
}

// ---------------------------------------------------------------------------
// CCA kernels (fp32; proven in R1/R3)
// ---------------------------------------------------------------------------
__global__ void __launch_bounds__(256) energyH_kernel(
    const float* __restrict__ qk, float* __restrict__ attn)
{
    const int w = blockIdx.x, b = blockIdx.y;
    __shared__ float Qs[64][65];
    __shared__ float Ks[64][65];
    const int tid = threadIdx.x;
    for (int l = tid; l < 4096; l += 256) {
        int c = l >> 6, h = l & 63;
        Qs[c][h] = qk[((size_t)(b * 128 + c)) * HW_ + h * 64 + w];
        Ks[c][h] = qk[((size_t)(b * 128 + 64 + c)) * HW_ + h * 64 + w];
    }
    __syncthreads();
    const int hh = tid & 63, ig = tid >> 6;
    float acc[16];
#pragma unroll
    for (int i = 0; i < 16; i++) acc[i] = 0.f;
    for (int c = 0; c < 64; c++) {
        float qv = Qs[c][hh];
#pragma unroll
        for (int i = 0; i < 16; i++) acc[i] += qv * Ks[c][ig * 16 + i];
    }
    float* orow = attn + (size_t)(((b * 64 + hh) * 64 + w)) * 128;
#pragma unroll
    for (int i = 0; i < 16; i++) {
        int ii = ig * 16 + i;
        orow[ii] = acc[i] + ((ii == hh) ? -1000000000.0f : 0.f);
    }
}

__global__ void __launch_bounds__(256) energyW_kernel(
    const float* __restrict__ qk, float* __restrict__ attn)
{
    const int h = blockIdx.x, b = blockIdx.y;
    __shared__ float Qs[64][65];
    __shared__ float Ks[64][65];
    const int tid = threadIdx.x;
    for (int l = tid; l < 4096; l += 256) {
        int c = l >> 6, w = l & 63;
        Qs[c][w] = qk[((size_t)(b * 128 + c)) * HW_ + h * 64 + w];
        Ks[c][w] = qk[((size_t)(b * 128 + 64 + c)) * HW_ + h * 64 + w];
    }
    __syncthreads();
    const int wq = tid & 63, jg = tid >> 6;
    float acc[16];
#pragma unroll
    for (int j = 0; j < 16; j++) acc[j] = 0.f;
    for (int c = 0; c < 64; c++) {
        float qv = Qs[c][wq];
#pragma unroll
        for (int j = 0; j < 16; j++) acc[j] += qv * Ks[c][jg * 16 + j];
    }
    float* orow = attn + (size_t)(((b * 64 + h) * 64 + wq)) * 128 + 64;
#pragma unroll
    for (int j = 0; j < 16; j++) orow[jg * 16 + j] = acc[j];
}

__global__ void __launch_bounds__(256) softmax_kernel(float* __restrict__ attn)
{
    int gw = (blockIdx.x * blockDim.x + threadIdx.x) >> 5;
    if (gw >= NPIX_) return;
    int lane = threadIdx.x & 31;
    float* row = attn + (size_t)gw * 128;
    float v0 = row[lane], v1 = row[lane + 32], v2 = row[lane + 64], v3 = row[lane + 96];
    float mx = fmaxf(fmaxf(v0, v1), fmaxf(v2, v3));
#pragma unroll
    for (int o = 16; o > 0; o >>= 1) mx = fmaxf(mx, __shfl_xor_sync(0xffffffffu, mx, o));
    v0 = expf(v0 - mx); v1 = expf(v1 - mx); v2 = expf(v2 - mx); v3 = expf(v3 - mx);
    float s = v0 + v1 + v2 + v3;
#pragma unroll
    for (int o = 16; o > 0; o >>= 1) s += __shfl_xor_sync(0xffffffffu, s, o);
    float inv = 1.0f / s;
    row[lane] = v0 * inv; row[lane + 32] = v1 * inv;
    row[lane + 64] = v2 * inv; row[lane + 96] = v3 * inv;
}

__global__ void __launch_bounds__(256) aggH_kernel(
    const float* __restrict__ v, const float* __restrict__ attn,
    const float* __restrict__ fin, float* __restrict__ fout,
    const float* __restrict__ gptr)
{
    const int w = blockIdx.x, b = blockIdx.y, cbk = blockIdx.z * 64;
    __shared__ float Vs[64][65];
    __shared__ float Am[64][65];
    const int tid = threadIdx.x;
    for (int l = tid; l < 4096; l += 256) {
        int c = l >> 6, i = l & 63;
        Vs[c][i] = v[(size_t)((b * 512 + cbk + c) * 64 + i) * 64 + w];
    }
    for (int l = tid; l < 4096; l += 256) {
        int h = l >> 6, i = l & 63;
        Am[h][i] = attn[(size_t)(((b * 64 + h) * 64 + w)) * 128 + i];
    }
    __syncthreads();
    const int tc = tid & 63, hg = tid >> 6;
    float acc[16];
#pragma unroll
    for (int t = 0; t < 16; t++) acc[t] = 0.f;
    for (int i = 0; i < 64; i++) {
        float vv = Vs[tc][i];
#pragma unroll
        for (int t = 0; t < 16; t++) acc[t] += vv * Am[hg * 16 + t][i];
    }
    const float g = *gptr;
#pragma unroll
    for (int t = 0; t < 16; t++) {
        int h = hg * 16 + t;
        size_t idx = (size_t)((b * 512 + cbk + tc) * 64 + h) * 64 + w;
        fout[idx] = fin[idx] + g * acc[t];
    }
}

__global__ void __launch_bounds__(256) aggW_kernel(
    const float* __restrict__ v, const float* __restrict__ attn,
    float* __restrict__ fout, const float* __restrict__ gptr)
{
    const int h = blockIdx.x, b = blockIdx.y, cbk = blockIdx.z * 64;
    __shared__ float Vs[64][65];
    __shared__ float Am[64][65];
    const int tid = threadIdx.x;
    for (int l = tid; l < 4096; l += 256) {
        int c = l >> 6, j = l & 63;
        Vs[c][j] = v[(size_t)((b * 512 + cbk + c) * 64 + h) * 64 + j];
    }
    for (int l = tid; l < 4096; l += 256) {
        int w = l >> 6, j = l & 63;
        Am[w][j] = attn[(size_t)(((b * 64 + h) * 64 + w)) * 128 + 64 + j];
    }
    __syncthreads();
    const int tc = tid & 63, wg = tid >> 6;
    float acc[16];
#pragma unroll
    for (int t = 0; t < 16; t++) acc[t] = 0.f;
    for (int j = 0; j < 64; j++) {
        float vv = Vs[tc][j];
#pragma unroll
        for (int t = 0; t < 16; t++) acc[t] += vv * Am[wg * 16 + t][j];
    }
    const float g = *gptr;
#pragma unroll
    for (int t = 0; t < 16; t++) {
        int w = wg * 16 + t;
        size_t idx = (size_t)((b * 512 + cbk + tc) * 64 + h) * 64 + w;
        fout[idx] += g * acc[t];
    }
}

// ---------------------------------------------------------------------------
// Launch
// ---------------------------------------------------------------------------
extern "C" void kernel_launch(void* const* d_in, const int* in_sizes, int n_in,
                              void* d_out, int out_size)
{
    const float* x     = (const float*)d_in[0];
    const float* c1w   = (const float*)d_in[1];
    const float* bn1g  = (const float*)d_in[2];
    const float* bn1b  = (const float*)d_in[3];
    const float* bn1m  = (const float*)d_in[4];
    const float* bn1v  = (const float*)d_in[5];
    const float* qw    = (const float*)d_in[6];
    const float* qb    = (const float*)d_in[7];
    const float* kw    = (const float*)d_in[8];
    const float* kb    = (const float*)d_in[9];
    const float* vw    = (const float*)d_in[10];
    const float* vb    = (const float*)d_in[11];
    const float* gamma = (const float*)d_in[12];
    const float* c2w   = (const float*)d_in[13];
    const float* bn2g  = (const float*)d_in[14];
    const float* bn2b  = (const float*)d_in[15];
    const float* bn2m  = (const float*)d_in[16];
    const float* bn2v  = (const float*)d_in[17];
    float* out = (float*)d_out;

    float *fA, *fB, *gv, *gqk, *gat, *gbqk;
    __nv_bfloat16 *xhi, *xlo, *fhi, *flo, *w1hi, *w1lo, *w2hi, *w2lo, *wqkhi, *wqklo, *wvhi, *wvlo;
    cudaGetSymbolAddress((void**)&fA, g_featsA);
    cudaGetSymbolAddress((void**)&fB, g_featsB);
    cudaGetSymbolAddress((void**)&gv, g_v);
    cudaGetSymbolAddress((void**)&gqk, g_qk);
    cudaGetSymbolAddress((void**)&gat, g_attn);
    cudaGetSymbolAddress((void**)&gbqk, g_bqk);
    cudaGetSymbolAddress((void**)&xhi, g_xhi);
    cudaGetSymbolAddress((void**)&xlo, g_xlo);
    cudaGetSymbolAddress((void**)&fhi, g_fhi);
    cudaGetSymbolAddress((void**)&flo, g_flo);
    cudaGetSymbolAddress((void**)&w1hi, g_w1hi);
    cudaGetSymbolAddress((void**)&w1lo, g_w1lo);
    cudaGetSymbolAddress((void**)&w2hi, g_w2hi);
    cudaGetSymbolAddress((void**)&w2lo, g_w2lo);
    cudaGetSymbolAddress((void**)&wqkhi, g_wqkhi);
    cudaGetSymbolAddress((void**)&wqklo, g_wqklo);
    cudaGetSymbolAddress((void**)&wvhi, g_wvhi);
    cudaGetSymbolAddress((void**)&wvlo, g_wvlo);

    const int SMEM_CG2 = 2 * 98304 + 1024;                         // 197632
    const int SMEM_P1  = 2 * (2 * 128 * 128 + 2 * 128 * 128) + 1024; // 132096
    cudaFuncSetAttribute(mma_conv_cg2<2048, 9, 1>, cudaFuncAttributeMaxDynamicSharedMemorySize, SMEM_CG2);
    cudaFuncSetAttribute(mma_conv_cg2<512, 9, 1>,  cudaFuncAttributeMaxDynamicSharedMemorySize, SMEM_CG2);
    cudaFuncSetAttribute(mma_conv_cg2<512, 1, 0>,  cudaFuncAttributeMaxDynamicSharedMemorySize, SMEM_CG2);
    cudaFuncSetAttribute(mma_proj_cg1<512, 0>,     cudaFuncAttributeMaxDynamicSharedMemorySize, SMEM_P1);

    // --- weight / bias prep ---
    prep_wconv<<<(512 * 2048 + 255) / 256, 256>>>(c1w, w1hi, w1lo, 512, 2048);
    prep_wconv<<<(512 * 512 + 255) / 256, 256>>>(c2w, w2hi, w2lo, 512, 512);
    prep_wlin<<<(64 * 512 + 255) / 256, 256>>>(qw, wqkhi, wqklo, 64 * 512);
    prep_wlin<<<(64 * 512 + 255) / 256, 256>>>(kw, wqkhi + 64 * 512, wqklo + 64 * 512, 64 * 512);
    prep_wlin<<<(512 * 512 + 255) / 256, 256>>>(vw, wvhi, wvlo, 512 * 512);
    prep_biasqk<<<1, 128>>>(qb, kb, gbqk);

    // --- conv1 + BN + ReLU ---
    prep_act<<<dim3(128, 64, 4), dim3(32, 8)>>>(x, xhi, xlo, 2048);
    mma_conv_cg2<2048, 9, 1><<<dim3(4, 32), 256, SMEM_CG2>>>(
        w1hi, w1lo, xhi, xlo, bn1g, bn1b, bn1m, bn1v, fA, 512);

    // --- 2x criss-cross attention ---
    float* cur = fA;
    float* nxt = fB;
    for (int it = 0; it < 2; ++it) {
        prep_act<<<dim3(128, 16, 4), dim3(32, 8)>>>(cur, fhi, flo, 512);
        mma_proj_cg1<512, 0><<<dim3(1, 128), 256, SMEM_P1>>>(
            wqkhi, wqklo, fhi, flo, gbqk, gqk, 128);
        mma_conv_cg2<512, 1, 0><<<dim3(4, 32), 256, SMEM_CG2>>>(
            wvhi, wvlo, fhi, flo, vb, nullptr, nullptr, nullptr, gv, 512);
        energyH_kernel<<<dim3(64, 4), 256>>>(gqk, gat);
        energyW_kernel<<<dim3(64, 4), 256>>>(gqk, gat);
        softmax_kernel<<<NPIX_ / 8, 256>>>(gat);
        aggH_kernel<<<dim3(64, 4, 8), 256>>>(gv, gat, cur, nxt, gamma);
        aggW_kernel<<<dim3(64, 4, 8), 256>>>(gv, gat, nxt, gamma);
        float* tmp = cur; cur = nxt; nxt = tmp;
    }

    // --- conv2 + BN + ReLU ---
    prep_act<<<dim3(128, 16, 4), dim3(32, 8)>>>(cur, fhi, flo, 512);
    mma_conv_cg2<512, 9, 1><<<dim3(4, 32), 256, SMEM_CG2>>>(
        w2hi, w2lo, fhi, flo, bn2g, bn2b, bn2m, bn2v, out, 512);
}